// round 14
// baseline (speedup 1.0000x reference)
#include <cuda_runtime.h>
#include <cstdint>

// out[n, d] = x[n, d] * w[d];  N = DIM = 8192, fp32.
// FINAL (verified 7x at 84.0us bench / ~76.5us kernel / 6.33-6.40 TB/s, rel_err 0).
//
// Exhaustive ceiling analysis R1-R13 (8 falsified levers): MLP depth,
// occupancy (20-70%), L2 read/write policies, sw-pipelining, 256-bit v8
// accesses, single-wave persistence, write-through stores. All structurally
// different kernels pin at or below the mixed 50/50 R/W HBM3e turnaround
// ceiling (~79-80% of 8 TB/s spec), with traffic at the 512 MiB algorithmic
// floor. LTS cap non-binding. The ~7.5us bench-vs-kernel gap is fixed
// graph-replay overhead, invariant across all variants.
//
// Structure: each thread owns one float4-column; weight loaded once into
// registers; 8 front-batched LDG.128 then 8 STG.128 per iteration;
// evict-first L2 policy both directions (writeback stores).

static constexpr int DIM   = 8192;
static constexpr int DIM4  = DIM / 4;              // 2048 float4 columns
static constexpr int THREADS = 256;
static constexpr int COLBLOCKS = DIM4 / THREADS;   // 8 column-blocks per row
static constexpr int ROWGROUPS = 256;
static constexpr int UNROLL = 8;

__global__ void __launch_bounds__(THREADS)
diag_scale_stream_kernel(const float4* __restrict__ x,
                         const float4* __restrict__ w4,
                         float4* __restrict__ out,
                         int n_rows)
{
    const int cb = blockIdx.x & (COLBLOCKS - 1);
    const int rg = blockIdx.x >> 3;
    const int col4 = cb * THREADS + threadIdx.x;

    const float4 wv = __ldg(&w4[col4]);            // once; stays in registers

    const long long rstride = (long long)ROWGROUPS * DIM4;   // elems between rows
    const float4* xp = x   + (long long)rg * DIM4 + col4;
    float4*       op = out + (long long)rg * DIM4 + col4;

    const int iters = n_rows / (ROWGROUPS * UNROLL);          // 4 for N=8192

    for (int it = 0; it < iters; ++it) {
        float4 v[UNROLL];
        #pragma unroll
        for (int u = 0; u < UNROLL; ++u)
            v[u] = __ldcs(xp + (long long)u * rstride);       // 8 reads in flight
        #pragma unroll
        for (int u = 0; u < UNROLL; ++u) {
            v[u].x *= wv.x;
            v[u].y *= wv.y;
            v[u].z *= wv.z;
            v[u].w *= wv.w;
            __stcs(op + (long long)u * rstride, v[u]);        // 8 writes
        }
        xp += (long long)UNROLL * rstride;
        op += (long long)UNROLL * rstride;
    }
}

// Generic fallback (correct for any shape).
__global__ void __launch_bounds__(256)
diag_scale_fallback(const float4* __restrict__ x,
                    const float4* __restrict__ w4,
                    float4* __restrict__ out,
                    long long n4, int dim4)
{
    long long i = (long long)blockIdx.x * blockDim.x + threadIdx.x;
    long long stride = (long long)gridDim.x * blockDim.x;
    for (; i < n4; i += stride) {
        float4 v = x[i];
        int col4 = (int)(i % dim4);
        float4 wv = __ldg(&w4[col4]);
        v.x *= wv.x; v.y *= wv.y; v.z *= wv.z; v.w *= wv.w;
        out[i] = v;
    }
}

extern "C" void kernel_launch(void* const* d_in, const int* in_sizes, int n_in,
                              void* d_out, int out_size)
{
    const float4* x  = (const float4*)d_in[0];
    const float4* w4 = (const float4*)d_in[1];
    float4* out = (float4*)d_out;

    long long n_elems = (long long)out_size;
    int dim = in_sizes[1];
    int n_rows = (int)(n_elems / dim);

    bool fast_ok = (dim == DIM) && (n_rows % (ROWGROUPS * UNROLL) == 0);

    if (fast_ok) {
        int blocks = COLBLOCKS * ROWGROUPS;    // 2048 blocks
        diag_scale_stream_kernel<<<blocks, THREADS>>>(x, w4, out, n_rows);
    } else {
        long long n4 = n_elems / 4;
        const int threads = 256;
        int blocks = 148 * 8 * 4;
        long long needed = (n4 + threads - 1) / threads;
        if ((long long)blocks > needed) blocks = (int)needed;
        diag_scale_fallback<<<blocks, threads>>>(x, w4, out, n4, dim / 4);
    }
}